// round 1
// baseline (speedup 1.0000x reference)
#include <cuda_runtime.h>
#include <cuda_bf16.h>
#include <math.h>

// Problem constants (DBRX-ish attention block)
#define TT      2048
#define DM      6144
#define NH      48
#define NKV     8
#define HD      128
#define QKV_N   8192            // DM + 2*NKV*HD
#define KV_OFF  DM              // 6144
#define V_OFF   (DM + NKV*HD)   // 7168
#define REP     (NH / NKV)      // 6
#define CLAMP_V 8.0f

// Scratch (static device globals; allocation-free per harness rules)
__device__ float g_qkv[TT * QKV_N];   // 64 MB
__device__ float g_attn[TT * DM];     // 48 MB

// ---------------------------------------------------------------------------
// SGEMM NT: C[M,N] = A[M,K] * B[N,K]^T   (both A,B row-major, K contiguous)
// 128x128 block tile, BK=8, 256 threads, 8x8 per-thread micro-tile.
// M,N multiples of 128; K multiple of 8. All fp32.
// ---------------------------------------------------------------------------
__global__ __launch_bounds__(256, 2)
void sgemm_nt(const float* __restrict__ A, const float* __restrict__ B,
              float* __restrict__ C, int M, int N, int K)
{
    __shared__ __align__(16) float As[8][128];
    __shared__ __align__(16) float Bs[8][128];

    const int tid = threadIdx.x;
    const int tx  = tid & 15;   // 0..15 -> N direction (8 cols each)
    const int ty  = tid >> 4;   // 0..15 -> M direction (8 rows each)

    const float* Ab = A + (size_t)blockIdx.y * 128 * K;
    const float* Bb = B + (size_t)blockIdx.x * 128 * K;

    const int lr = tid >> 1;        // 0..127 (row within tile)
    const int lc = (tid & 1) * 4;   // 0 or 4 (k offset)

    float acc[8][8];
#pragma unroll
    for (int i = 0; i < 8; i++)
#pragma unroll
        for (int j = 0; j < 8; j++) acc[i][j] = 0.f;

    for (int k0 = 0; k0 < K; k0 += 8) {
        float4 a4 = *(const float4*)(Ab + (size_t)lr * K + k0 + lc);
        float4 b4 = *(const float4*)(Bb + (size_t)lr * K + k0 + lc);
        As[lc + 0][lr] = a4.x; As[lc + 1][lr] = a4.y;
        As[lc + 2][lr] = a4.z; As[lc + 3][lr] = a4.w;
        Bs[lc + 0][lr] = b4.x; Bs[lc + 1][lr] = b4.y;
        Bs[lc + 2][lr] = b4.z; Bs[lc + 3][lr] = b4.w;
        __syncthreads();

#pragma unroll
        for (int kk = 0; kk < 8; kk++) {
            float ar[8], br[8];
            *(float4*)(ar)     = *(const float4*)&As[kk][ty * 8];
            *(float4*)(ar + 4) = *(const float4*)&As[kk][ty * 8 + 4];
            *(float4*)(br)     = *(const float4*)&Bs[kk][tx * 8];
            *(float4*)(br + 4) = *(const float4*)&Bs[kk][tx * 8 + 4];
#pragma unroll
            for (int i = 0; i < 8; i++)
#pragma unroll
                for (int j = 0; j < 8; j++)
                    acc[i][j] = fmaf(ar[i], br[j], acc[i][j]);
        }
        __syncthreads();
    }

    float* Cb = C + (size_t)(blockIdx.y * 128 + ty * 8) * N + blockIdx.x * 128 + tx * 8;
#pragma unroll
    for (int i = 0; i < 8; i++) {
        *(float4*)(Cb + (size_t)i * N)     = *(const float4*)&acc[i][0];
        *(float4*)(Cb + (size_t)i * N + 4) = *(const float4*)&acc[i][4];
    }
}

// ---------------------------------------------------------------------------
// RoPE (interleaved pairs, exponent 2i/rd) + clamp, in-place on g_qkv.
// One thread per pair. Grid: (16, TT), block 256 -> p in [0, 4096).
//   p <  3072          : Q pairs (48 heads * 64 pairs)
//   p in [3072, 3584)  : K pairs (8 heads * 64 pairs)
//   p >= 3584          : V (just clamp, 2 elements per thread)
// ---------------------------------------------------------------------------
__global__ __launch_bounds__(256)
void rope_clamp_kernel()
{
    const int t = blockIdx.y;
    const int p = blockIdx.x * blockDim.x + threadIdx.x;
    float* row = g_qkv + (size_t)t * QKV_N;

    if (p < 3584) {
        int col, i;
        if (p < 3072) { col = 2 * p;               i = p & 63; }
        else          { int pp = p - 3072; col = KV_OFF + 2 * pp; i = pp & 63; }
        float a = row[col];
        float b = row[col + 1];
        // inv_freq = base^(-2i/128) = base^(-i/64); double pow -> correctly rounded
        float inv = (float)pow(500000.0, -(double)i / 64.0);
        float f = (float)t * inv;
        float s, c;
        sincosf(f, &s, &c);
        float a2 = a * c - b * s;
        float b2 = a * s + b * c;
        row[col]     = fminf(fmaxf(a2, -CLAMP_V), CLAMP_V);
        row[col + 1] = fminf(fmaxf(b2, -CLAMP_V), CLAMP_V);
    } else {
        int pp  = p - 3584;               // 0..511
        int col = V_OFF + 2 * pp;
        row[col]     = fminf(fmaxf(row[col],     -CLAMP_V), CLAMP_V);
        row[col + 1] = fminf(fmaxf(row[col + 1], -CLAMP_V), CLAMP_V);
    }
}

// ---------------------------------------------------------------------------
// Flash-style causal attention. One block = (64 q rows, one head).
// Online softmax; O accumulator in registers (4 rows x 8 cols per thread).
// Reads Q/K/V directly from g_qkv (strided rows), writes g_attn [T, DM].
// ---------------------------------------------------------------------------
#define AQ 64
#define AK 64

struct __align__(16) AttnSmem {
    float Qs[AQ][HD];
    float Ks[AK][HD];
    float Vs[AK][HD];
    float Ss[AQ][AK];
    float rowM[AQ];
    float rowL[AQ];
    float rowA[AQ];
};

__global__ __launch_bounds__(256)
void attn_kernel(float* __restrict__ out)
{
    extern __shared__ char smraw[];
    AttnSmem& sm = *reinterpret_cast<AttnSmem*>(smraw);

    const int qb  = blockIdx.x;       // q tile (32)
    const int h   = blockIdx.y;       // head (48)
    const int kh  = h / REP;          // kv head
    const int tid = threadIdx.x;
    const int tx  = tid & 15;
    const int ty  = tid >> 4;
    const int r0  = ty * 4;           // this thread's 4 rows
    const int oc0 = tx * 8;           // this thread's 8 output cols
    const float scale = 0.088388347648318447f;   // 1/sqrt(128)

    // Load Q tile (64 x 128)
    {
        const float* qbase = g_qkv + (size_t)(qb * AQ) * QKV_N + h * HD;
#pragma unroll
        for (int i = 0; i < 8; i++) {
            int f = tid + i * 256;        // float4 index 0..2047
            int r = f >> 5;
            int d = (f & 31) * 4;
            *(float4*)&sm.Qs[r][d] = *(const float4*)(qbase + (size_t)r * QKV_N + d);
        }
    }
    if (tid < AQ) { sm.rowM[tid] = -1e30f; sm.rowL[tid] = 0.f; }

    float o[4][8];
#pragma unroll
    for (int i = 0; i < 4; i++)
#pragma unroll
        for (int j = 0; j < 8; j++) o[i][j] = 0.f;

    __syncthreads();

    for (int kt = 0; kt <= qb; kt++) {
        // Load K/V tiles
        {
            const float* kbase = g_qkv + (size_t)(kt * AK) * QKV_N + KV_OFF + kh * HD;
            const float* vbase = g_qkv + (size_t)(kt * AK) * QKV_N + V_OFF  + kh * HD;
#pragma unroll
            for (int i = 0; i < 8; i++) {
                int f = tid + i * 256;
                int r = f >> 5;
                int d = (f & 31) * 4;
                *(float4*)&sm.Ks[r][d] = *(const float4*)(kbase + (size_t)r * QKV_N + d);
                *(float4*)&sm.Vs[r][d] = *(const float4*)(vbase + (size_t)r * QKV_N + d);
            }
        }
        __syncthreads();

        // S = Q K^T (each thread 4 rows x 4 cols)
        const int c0 = tx * 4;
        float s[4][4];
#pragma unroll
        for (int i = 0; i < 4; i++)
#pragma unroll
            for (int j = 0; j < 4; j++) s[i][j] = 0.f;

        for (int d = 0; d < HD; d += 4) {
            float4 qv[4], kv[4];
#pragma unroll
            for (int i = 0; i < 4; i++) qv[i] = *(const float4*)&sm.Qs[r0 + i][d];
#pragma unroll
            for (int j = 0; j < 4; j++) kv[j] = *(const float4*)&sm.Ks[c0 + j][d];
#pragma unroll
            for (int i = 0; i < 4; i++)
#pragma unroll
                for (int j = 0; j < 4; j++) {
                    s[i][j] = fmaf(qv[i].x, kv[j].x, s[i][j]);
                    s[i][j] = fmaf(qv[i].y, kv[j].y, s[i][j]);
                    s[i][j] = fmaf(qv[i].z, kv[j].z, s[i][j]);
                    s[i][j] = fmaf(qv[i].w, kv[j].w, s[i][j]);
                }
        }

        const bool diag = (kt == qb);
#pragma unroll
        for (int i = 0; i < 4; i++)
#pragma unroll
            for (int j = 0; j < 4; j++) {
                float v = s[i][j] * scale;
                if (diag && (c0 + j) > (r0 + i)) v = -1e30f;   // causal mask
                sm.Ss[r0 + i][c0 + j] = v;
            }
        __syncthreads();

        // Online softmax (one thread per row)
        if (tid < AQ) {
            float mOld = sm.rowM[tid];
            float m = mOld;
#pragma unroll 8
            for (int j = 0; j < AK; j++) m = fmaxf(m, sm.Ss[tid][j]);
            float alpha = __expf(mOld - m);
            float l = 0.f;
#pragma unroll 8
            for (int j = 0; j < AK; j++) {
                float pe = __expf(sm.Ss[tid][j] - m);
                sm.Ss[tid][j] = pe;
                l += pe;
            }
            sm.rowL[tid] = sm.rowL[tid] * alpha + l;
            sm.rowM[tid] = m;
            sm.rowA[tid] = alpha;
        }
        __syncthreads();

        // O = alpha * O + P @ V (each thread 4 rows x 8 cols)
        float al[4];
#pragma unroll
        for (int i = 0; i < 4; i++) al[i] = sm.rowA[r0 + i];
#pragma unroll
        for (int i = 0; i < 4; i++)
#pragma unroll
            for (int j = 0; j < 8; j++) o[i][j] *= al[i];

        for (int jj = 0; jj < AK; jj++) {
            float p0 = sm.Ss[r0 + 0][jj];
            float p1 = sm.Ss[r0 + 1][jj];
            float p2 = sm.Ss[r0 + 2][jj];
            float p3 = sm.Ss[r0 + 3][jj];
            float4 va = *(const float4*)&sm.Vs[jj][oc0];
            float4 vb = *(const float4*)&sm.Vs[jj][oc0 + 4];
            float vv[8] = {va.x, va.y, va.z, va.w, vb.x, vb.y, vb.z, vb.w};
#pragma unroll
            for (int j = 0; j < 8; j++) {
                o[0][j] = fmaf(p0, vv[j], o[0][j]);
                o[1][j] = fmaf(p1, vv[j], o[1][j]);
                o[2][j] = fmaf(p2, vv[j], o[2][j]);
                o[3][j] = fmaf(p3, vv[j], o[3][j]);
            }
        }
        __syncthreads();
    }

    // Normalize and write: out[t, h*HD + c]
#pragma unroll
    for (int i = 0; i < 4; i++) {
        float rl = 1.f / sm.rowL[r0 + i];
        int tg = qb * AQ + r0 + i;
        float* dst = out + (size_t)tg * DM + h * HD + oc0;
        float4 w0, w1;
        w0.x = o[i][0] * rl; w0.y = o[i][1] * rl; w0.z = o[i][2] * rl; w0.w = o[i][3] * rl;
        w1.x = o[i][4] * rl; w1.y = o[i][5] * rl; w1.z = o[i][6] * rl; w1.w = o[i][7] * rl;
        *(float4*)(dst)     = w0;
        *(float4*)(dst + 4) = w1;
    }
}

// ---------------------------------------------------------------------------
// Launch: qkv gemm -> rope/clamp (in-place) -> flash attention -> out gemm
// Inputs: d_in[0]=x [1,2048,6144], d_in[1]=causal_mask (unused),
//         d_in[2]=w_qkv [8192,6144], d_in[3]=w_out [6144,6144]
// ---------------------------------------------------------------------------
extern "C" void kernel_launch(void* const* d_in, const int* in_sizes, int n_in,
                              void* d_out, int out_size)
{
    const float* x     = (const float*)d_in[0];
    const float* w_qkv = (const float*)d_in[2];
    const float* w_out = (const float*)d_in[3];
    float* out = (float*)d_out;

    float* qkv;  cudaGetSymbolAddress((void**)&qkv,  g_qkv);
    float* attn; cudaGetSymbolAddress((void**)&attn, g_attn);

    // 1) QKV projection: [2048,8192] = x[2048,6144] @ w_qkv[8192,6144]^T
    {
        dim3 grid(QKV_N / 128, TT / 128);
        sgemm_nt<<<grid, 256>>>(x, w_qkv, qkv, TT, QKV_N, DM);
    }

    // 2) RoPE + clamp in place
    {
        dim3 grid(16, TT);
        rope_clamp_kernel<<<grid, 256>>>();
    }

    // 3) Attention
    {
        static int smem_bytes = (int)sizeof(AttnSmem);
        cudaFuncSetAttribute(attn_kernel,
                             cudaFuncAttributeMaxDynamicSharedMemorySize, smem_bytes);
        dim3 grid(TT / AQ, NH);
        attn_kernel<<<grid, 256, smem_bytes>>>(attn);
    }

    // 4) Output projection: [2048,6144] = attn[2048,6144] @ w_out[6144,6144]^T
    {
        dim3 grid(DM / 128, TT / 128);
        sgemm_nt<<<grid, 256>>>(attn, w_out, out, TT, DM, DM);
    }
}

// round 3
// speedup vs baseline: 1.7554x; 1.7554x over previous
#include <cuda_runtime.h>
#include <cuda_bf16.h>
#include <math.h>
#include <stdint.h>

// Problem constants
#define TT      2048
#define DM      6144
#define NH      48
#define NKV     8
#define HD      128
#define QKV_N   8192
#define KV_OFF  DM
#define V_OFF   (DM + NKV*HD)
#define REP     (NH / NKV)
#define CLAMP_V 8.0f

// Scratch (static device globals; allocation-free per harness rules)
__device__ float g_qkv[(size_t)TT * QKV_N];     // 64 MB
__device__ float g_attn[(size_t)TT * DM];       // 48 MB (tf32-rounded at write)
__device__ float g_xr[(size_t)TT * DM];         // rna-tf32(x)
__device__ float g_wqkvr[(size_t)QKV_N * DM];   // rna-tf32(w_qkv)
__device__ float g_woutr[(size_t)DM * DM];      // rna-tf32(w_out)

// ===========================================================================
// Helpers
// ===========================================================================
__device__ __forceinline__ uint32_t smem_to_u32(const void* p) {
    uint32_t a;
    asm("{ .reg .u64 t; cvta.to.shared.u64 t, %1; cvt.u32.u64 %0, t; }"
        : "=r"(a) : "l"(p));
    return a;
}
__device__ __forceinline__ void cp16(uint32_t s, const void* g) {
    asm volatile("cp.async.cg.shared.global [%0], [%1], 16;"
                 :: "r"(s), "l"(g) : "memory");
}
__device__ __forceinline__ float ftf32(float x) {
    uint32_t o, i = __float_as_uint(x);
    asm("cvt.rna.tf32.f32 %0, %1;" : "=r"(o) : "r"(i));
    return __uint_as_float(o);
}
__device__ __forceinline__ void mma8(float* d, const uint32_t* a, const uint32_t* b) {
    asm volatile(
        "mma.sync.aligned.m16n8k8.row.col.f32.tf32.tf32.f32 "
        "{%0,%1,%2,%3}, {%4,%5,%6,%7}, {%8,%9}, {%0,%1,%2,%3};"
        : "+f"(d[0]), "+f"(d[1]), "+f"(d[2]), "+f"(d[3])
        : "r"(a[0]), "r"(a[1]), "r"(a[2]), "r"(a[3]), "r"(b[0]), "r"(b[1]));
}

// ===========================================================================
// Elementwise rna-tf32 rounding pass
// ===========================================================================
__global__ __launch_bounds__(256)
void round_tf32_kernel(const float4* __restrict__ src, float4* __restrict__ dst, int n4)
{
    int i = blockIdx.x * blockDim.x + threadIdx.x;
    if (i < n4) {
        float4 v = src[i];
        v.x = ftf32(v.x); v.y = ftf32(v.y); v.z = ftf32(v.z); v.w = ftf32(v.w);
        dst[i] = v;
    }
}

// ===========================================================================
// tf32 mma.sync GEMM: C[M,N] = A[M,K] * B[N,K]^T  (both K-major, tf32-rounded)
// 128x128 CTA tile, BK=32, 8 warps (64x32 warp tile), double-buffered cp.async.
// Smem rows padded to 36 floats -> conflict-free fragment loads.
// ===========================================================================
#define GPAD 36
#define SM_STRIDE (128 * GPAD)           // floats per buffer per operand
#define GEMM_SMEM_BYTES (4 * SM_STRIDE * 4)   // 2 bufs x 2 operands = 73728 B

__global__ __launch_bounds__(256)
void gemm_mma(const float* __restrict__ A, const float* __restrict__ B,
              float* __restrict__ C, int N, int K)
{
    extern __shared__ float sm[];
    const int tid  = threadIdx.x;
    const int wid  = tid >> 5, lane = tid & 31;
    const int wm   = (wid >> 2) * 64;    // warp row offset
    const int wn   = (wid & 3) * 32;     // warp col offset
    const int gr   = lane >> 2, tc = lane & 3;
    const int bm   = blockIdx.y * 128, bn = blockIdx.x * 128;

    const int ldr = tid >> 3;            // 0..31
    const int ldc = (tid & 7) * 4;       // 0..28

    const uint32_t sbase = smem_to_u32(sm);
    const int NS = K / 32;

    float acc[4][4][4];
#pragma unroll
    for (int i = 0; i < 4; i++)
#pragma unroll
        for (int j = 0; j < 4; j++)
#pragma unroll
            for (int r = 0; r < 4; r++) acc[i][j][r] = 0.f;

    // async load of one 128x32 slice pair into buffer `buf`
    auto loadTiles = [&](int k0, int buf) {
#pragma unroll
        for (int v = 0; v < 4; v++) {
            int row = ldr + v * 32;
            uint32_t sa = sbase + (uint32_t)(buf * SM_STRIDE + row * GPAD + ldc) * 4;
            cp16(sa, A + (size_t)(bm + row) * K + k0 + ldc);
            uint32_t sb = sbase + (uint32_t)(2 * SM_STRIDE + buf * SM_STRIDE + row * GPAD + ldc) * 4;
            cp16(sb, B + (size_t)(bn + row) * K + k0 + ldc);
        }
        asm volatile("cp.async.commit_group;" ::: "memory");
    };

    loadTiles(0, 0);

    for (int s = 0; s < NS; s++) {
        const int buf = s & 1;
        if (s + 1 < NS) {
            loadTiles((s + 1) * 32, buf ^ 1);
            asm volatile("cp.async.wait_group 1;" ::: "memory");
        } else {
            asm volatile("cp.async.wait_group 0;" ::: "memory");
        }
        __syncthreads();

        const float* As_ = sm + buf * SM_STRIDE;
        const float* Bs_ = sm + 2 * SM_STRIDE + buf * SM_STRIDE;

#pragma unroll
        for (int ks = 0; ks < 4; ks++) {
            uint32_t a[4][4], b[4][2];
#pragma unroll
            for (int i = 0; i < 4; i++) {
                const float* ap = As_ + (wm + i * 16 + gr) * GPAD + ks * 8 + tc;
                a[i][0] = __float_as_uint(ap[0]);
                a[i][1] = __float_as_uint(ap[8 * GPAD]);
                a[i][2] = __float_as_uint(ap[4]);
                a[i][3] = __float_as_uint(ap[8 * GPAD + 4]);
            }
#pragma unroll
            for (int j = 0; j < 4; j++) {
                const float* bp = Bs_ + (wn + j * 8 + gr) * GPAD + ks * 8 + tc;
                b[j][0] = __float_as_uint(bp[0]);
                b[j][1] = __float_as_uint(bp[4]);
            }
#pragma unroll
            for (int i = 0; i < 4; i++)
#pragma unroll
                for (int j = 0; j < 4; j++)
                    mma8(acc[i][j], a[i], b[j]);
        }
        __syncthreads();
    }

    // Epilogue: per-fragment float2 stores
#pragma unroll
    for (int i = 0; i < 4; i++) {
#pragma unroll
        for (int j = 0; j < 4; j++) {
            int r = bm + wm + i * 16 + gr;
            int c = bn + wn + j * 8 + tc * 2;
            float2 v0 = make_float2(acc[i][j][0], acc[i][j][1]);
            float2 v1 = make_float2(acc[i][j][2], acc[i][j][3]);
            *(float2*)&C[(size_t)r * N + c]       = v0;
            *(float2*)&C[(size_t)(r + 8) * N + c] = v1;
        }
    }
}

// ===========================================================================
// RoPE + clamp (in-place on g_qkv)
// ===========================================================================
__global__ __launch_bounds__(256)
void rope_clamp_kernel()
{
    const int t = blockIdx.y;
    const int p = blockIdx.x * blockDim.x + threadIdx.x;
    float* row = g_qkv + (size_t)t * QKV_N;

    if (p < 3584) {
        int col, i;
        if (p < 3072) { col = 2 * p;               i = p & 63; }
        else          { int pp = p - 3072; col = KV_OFF + 2 * pp; i = pp & 63; }
        float a = row[col];
        float b = row[col + 1];
        float inv = (float)pow(500000.0, -(double)i / 64.0);
        float f = (float)t * inv;
        float s, c;
        sincosf(f, &s, &c);
        float a2 = a * c - b * s;
        float b2 = a * s + b * c;
        row[col]     = fminf(fmaxf(a2, -CLAMP_V), CLAMP_V);
        row[col + 1] = fminf(fmaxf(b2, -CLAMP_V), CLAMP_V);
    } else {
        int pp  = p - 3584;
        int col = V_OFF + 2 * pp;
        row[col]     = fminf(fmaxf(row[col],     -CLAMP_V), CLAMP_V);
        row[col + 1] = fminf(fmaxf(row[col + 1], -CLAMP_V), CLAMP_V);
    }
}

// ===========================================================================
// Flash-style causal attention (fp32 SIMT) — output rna-tf32 rounded
// ===========================================================================
#define AQ 64
#define AK 64

struct __align__(16) AttnSmem {
    float Qs[AQ][HD];
    float Ks[AK][HD];
    float Vs[AK][HD];
    float Ss[AQ][AK];
    float rowM[AQ];
    float rowL[AQ];
    float rowA[AQ];
};

__global__ __launch_bounds__(256)
void attn_kernel(float* __restrict__ out)
{
    extern __shared__ char smraw[];
    AttnSmem& sm = *reinterpret_cast<AttnSmem*>(smraw);

    const int qb  = blockIdx.x;
    const int h   = blockIdx.y;
    const int kh  = h / REP;
    const int tid = threadIdx.x;
    const int tx  = tid & 15;
    const int ty  = tid >> 4;
    const int r0  = ty * 4;
    const int oc0 = tx * 8;
    const float scale = 0.088388347648318447f;

    {
        const float* qbase = g_qkv + (size_t)(qb * AQ) * QKV_N + h * HD;
#pragma unroll
        for (int i = 0; i < 8; i++) {
            int f = tid + i * 256;
            int r = f >> 5;
            int d = (f & 31) * 4;
            *(float4*)&sm.Qs[r][d] = *(const float4*)(qbase + (size_t)r * QKV_N + d);
        }
    }
    if (tid < AQ) { sm.rowM[tid] = -1e30f; sm.rowL[tid] = 0.f; }

    float o[4][8];
#pragma unroll
    for (int i = 0; i < 4; i++)
#pragma unroll
        for (int j = 0; j < 8; j++) o[i][j] = 0.f;

    __syncthreads();

    for (int kt = 0; kt <= qb; kt++) {
        {
            const float* kbase = g_qkv + (size_t)(kt * AK) * QKV_N + KV_OFF + kh * HD;
            const float* vbase = g_qkv + (size_t)(kt * AK) * QKV_N + V_OFF  + kh * HD;
#pragma unroll
            for (int i = 0; i < 8; i++) {
                int f = tid + i * 256;
                int r = f >> 5;
                int d = (f & 31) * 4;
                *(float4*)&sm.Ks[r][d] = *(const float4*)(kbase + (size_t)r * QKV_N + d);
                *(float4*)&sm.Vs[r][d] = *(const float4*)(vbase + (size_t)r * QKV_N + d);
            }
        }
        __syncthreads();

        const int c0 = tx * 4;
        float s[4][4];
#pragma unroll
        for (int i = 0; i < 4; i++)
#pragma unroll
            for (int j = 0; j < 4; j++) s[i][j] = 0.f;

        for (int d = 0; d < HD; d += 4) {
            float4 qv[4], kv[4];
#pragma unroll
            for (int i = 0; i < 4; i++) qv[i] = *(const float4*)&sm.Qs[r0 + i][d];
#pragma unroll
            for (int j = 0; j < 4; j++) kv[j] = *(const float4*)&sm.Ks[c0 + j][d];
#pragma unroll
            for (int i = 0; i < 4; i++)
#pragma unroll
                for (int j = 0; j < 4; j++) {
                    s[i][j] = fmaf(qv[i].x, kv[j].x, s[i][j]);
                    s[i][j] = fmaf(qv[i].y, kv[j].y, s[i][j]);
                    s[i][j] = fmaf(qv[i].z, kv[j].z, s[i][j]);
                    s[i][j] = fmaf(qv[i].w, kv[j].w, s[i][j]);
                }
        }

        const bool diag = (kt == qb);
#pragma unroll
        for (int i = 0; i < 4; i++)
#pragma unroll
            for (int j = 0; j < 4; j++) {
                float v = s[i][j] * scale;
                if (diag && (c0 + j) > (r0 + i)) v = -1e30f;
                sm.Ss[r0 + i][c0 + j] = v;
            }
        __syncthreads();

        if (tid < AQ) {
            float mOld = sm.rowM[tid];
            float m = mOld;
#pragma unroll 8
            for (int j = 0; j < AK; j++) m = fmaxf(m, sm.Ss[tid][j]);
            float alpha = __expf(mOld - m);
            float l = 0.f;
#pragma unroll 8
            for (int j = 0; j < AK; j++) {
                float pe = __expf(sm.Ss[tid][j] - m);
                sm.Ss[tid][j] = pe;
                l += pe;
            }
            sm.rowL[tid] = sm.rowL[tid] * alpha + l;
            sm.rowM[tid] = m;
            sm.rowA[tid] = alpha;
        }
        __syncthreads();

        float al[4];
#pragma unroll
        for (int i = 0; i < 4; i++) al[i] = sm.rowA[r0 + i];
#pragma unroll
        for (int i = 0; i < 4; i++)
#pragma unroll
            for (int j = 0; j < 8; j++) o[i][j] *= al[i];

        for (int jj = 0; jj < AK; jj++) {
            float p0 = sm.Ss[r0 + 0][jj];
            float p1 = sm.Ss[r0 + 1][jj];
            float p2 = sm.Ss[r0 + 2][jj];
            float p3 = sm.Ss[r0 + 3][jj];
            float4 va = *(const float4*)&sm.Vs[jj][oc0];
            float4 vb = *(const float4*)&sm.Vs[jj][oc0 + 4];
            float vv[8] = {va.x, va.y, va.z, va.w, vb.x, vb.y, vb.z, vb.w};
#pragma unroll
            for (int j = 0; j < 8; j++) {
                o[0][j] = fmaf(p0, vv[j], o[0][j]);
                o[1][j] = fmaf(p1, vv[j], o[1][j]);
                o[2][j] = fmaf(p2, vv[j], o[2][j]);
                o[3][j] = fmaf(p3, vv[j], o[3][j]);
            }
        }
        __syncthreads();
    }

#pragma unroll
    for (int i = 0; i < 4; i++) {
        float rl = 1.f / sm.rowL[r0 + i];
        int tg = qb * AQ + r0 + i;
        float* dst = out + (size_t)tg * DM + h * HD + oc0;
        float4 w0, w1;
        w0.x = ftf32(o[i][0] * rl); w0.y = ftf32(o[i][1] * rl);
        w0.z = ftf32(o[i][2] * rl); w0.w = ftf32(o[i][3] * rl);
        w1.x = ftf32(o[i][4] * rl); w1.y = ftf32(o[i][5] * rl);
        w1.z = ftf32(o[i][6] * rl); w1.w = ftf32(o[i][7] * rl);
        *(float4*)(dst)     = w0;
        *(float4*)(dst + 4) = w1;
    }
}

// ===========================================================================
// Host side
// ===========================================================================
extern "C" void kernel_launch(void* const* d_in, const int* in_sizes, int n_in,
                              void* d_out, int out_size)
{
    const float* x     = (const float*)d_in[0];
    const float* w_qkv = (const float*)d_in[2];
    const float* w_out = (const float*)d_in[3];
    float* out = (float*)d_out;

    float *qkv, *attn, *xr, *wqkvr, *woutr;
    cudaGetSymbolAddress((void**)&qkv,   g_qkv);
    cudaGetSymbolAddress((void**)&attn,  g_attn);
    cudaGetSymbolAddress((void**)&xr,    g_xr);
    cudaGetSymbolAddress((void**)&wqkvr, g_wqkvr);
    cudaGetSymbolAddress((void**)&woutr, g_woutr);

    // 0) rna-tf32 round GEMM operands
    {
        int n4x = TT * DM / 4;
        round_tf32_kernel<<<(n4x + 255) / 256, 256>>>((const float4*)x, (float4*)xr, n4x);
        int n4q = QKV_N * DM / 4;
        round_tf32_kernel<<<(n4q + 255) / 256, 256>>>((const float4*)w_qkv, (float4*)wqkvr, n4q);
        int n4o = DM * DM / 4;
        round_tf32_kernel<<<(n4o + 255) / 256, 256>>>((const float4*)w_out, (float4*)woutr, n4o);
    }

    cudaFuncSetAttribute(gemm_mma, cudaFuncAttributeMaxDynamicSharedMemorySize,
                         GEMM_SMEM_BYTES);

    // 1) QKV projection (tensor cores via mma.sync tf32)
    {
        dim3 grid(QKV_N / 128, TT / 128);
        gemm_mma<<<grid, 256, GEMM_SMEM_BYTES>>>(xr, wqkvr, qkv, QKV_N, DM);
    }

    // 2) RoPE + clamp
    {
        dim3 grid(16, TT);
        rope_clamp_kernel<<<grid, 256>>>();
    }

    // 3) Attention (fp32 SIMT, writes tf32-rounded)
    {
        int smem_bytes = (int)sizeof(AttnSmem);
        cudaFuncSetAttribute(attn_kernel, cudaFuncAttributeMaxDynamicSharedMemorySize, smem_bytes);
        dim3 grid(TT / AQ, NH);
        attn_kernel<<<grid, 256, smem_bytes>>>(attn);
    }

    // 4) Output projection (tensor cores via mma.sync tf32)
    {
        dim3 grid(DM / 128, TT / 128);
        gemm_mma<<<grid, 256, GEMM_SMEM_BYTES>>>(attn, woutr, out, DM, DM);
    }
}

// round 4
// speedup vs baseline: 3.1823x; 1.8128x over previous
#include <cuda_runtime.h>
#include <cuda_bf16.h>
#include <math.h>
#include <stdint.h>

// Problem constants
#define TT      2048
#define DM      6144
#define NH      48
#define NKV     8
#define HD      128
#define QKV_N   8192
#define KV_OFF  DM
#define V_OFF   (DM + NKV*HD)
#define REP     (NH / NKV)
#define CLAMP_V 8.0f

// Scratch
__device__ float g_qkv[(size_t)TT * QKV_N];     // 64 MB
__device__ float g_attn[(size_t)TT * DM];       // 48 MB

// ===========================================================================
// Helpers
// ===========================================================================
__device__ __forceinline__ uint32_t smem_to_u32(const void* p) {
    uint32_t a;
    asm("{ .reg .u64 t; cvta.to.shared.u64 t, %1; cvt.u32.u64 %0, t; }"
        : "=r"(a) : "l"(p));
    return a;
}
__device__ __forceinline__ void cp16(uint32_t s, const void* g) {
    asm volatile("cp.async.cg.shared.global [%0], [%1], 16;"
                 :: "r"(s), "l"(g) : "memory");
}
__device__ __forceinline__ float ftf32(float x) {
    uint32_t o, i = __float_as_uint(x);
    asm("cvt.rna.tf32.f32 %0, %1;" : "=r"(o) : "r"(i));
    return __uint_as_float(o);
}
__device__ __forceinline__ uint32_t utf32(float x) {
    uint32_t o, i = __float_as_uint(x);
    asm("cvt.rna.tf32.f32 %0, %1;" : "=r"(o) : "r"(i));
    return o;
}
// tf32 m16n8k8 mma
__device__ __forceinline__ void mma8(float* d, const uint32_t* a, const uint32_t* b) {
    asm volatile(
        "mma.sync.aligned.m16n8k8.row.col.f32.tf32.tf32.f32 "
        "{%0,%1,%2,%3}, {%4,%5,%6,%7}, {%8,%9}, {%0,%1,%2,%3};"
        : "+f"(d[0]), "+f"(d[1]), "+f"(d[2]), "+f"(d[3])
        : "r"(a[0]), "r"(a[1]), "r"(a[2]), "r"(a[3]), "r"(b[0]), "r"(b[1]));
}
// bf16 m16n8k16 mma
__device__ __forceinline__ void mma16bf(float* d, const uint32_t* a, const uint32_t* b) {
    asm volatile(
        "mma.sync.aligned.m16n8k16.row.col.f32.bf16.bf16.f32 "
        "{%0,%1,%2,%3}, {%4,%5,%6,%7}, {%8,%9}, {%0,%1,%2,%3};"
        : "+f"(d[0]), "+f"(d[1]), "+f"(d[2]), "+f"(d[3])
        : "r"(a[0]), "r"(a[1]), "r"(a[2]), "r"(a[3]), "r"(b[0]), "r"(b[1]));
}
// split (x,y) into packed bf16x2 hi word (ret) + lo word
__device__ __forceinline__ uint32_t packsplit(float x, float y, uint32_t& lo) {
    __nv_bfloat16 hx = __float2bfloat16(x);
    __nv_bfloat16 hy = __float2bfloat16(y);
    float rx = x - __bfloat162float(hx);
    float ry = y - __bfloat162float(hy);
    __nv_bfloat16 lx = __float2bfloat16(rx);
    __nv_bfloat16 ly = __float2bfloat16(ry);
    lo = ((uint32_t)__bfloat16_as_ushort(ly) << 16) | __bfloat16_as_ushort(lx);
    return ((uint32_t)__bfloat16_as_ushort(hy) << 16) | __bfloat16_as_ushort(hx);
}

// ===========================================================================
// tf32 mma.sync GEMM: C[M,N] = A[M,K] * B[N,K]^T  (raw fp32 in, rna-tf32 in-reg)
// ===========================================================================
#define GPAD 36
#define SM_STRIDE (128 * GPAD)
#define GEMM_SMEM_BYTES (4 * SM_STRIDE * 4)

__global__ __launch_bounds__(256)
void gemm_mma(const float* __restrict__ A, const float* __restrict__ B,
              float* __restrict__ C, int N, int K)
{
    extern __shared__ float sm[];
    const int tid  = threadIdx.x;
    const int wid  = tid >> 5, lane = tid & 31;
    const int wm   = (wid >> 2) * 64;
    const int wn   = (wid & 3) * 32;
    const int gr   = lane >> 2, tc = lane & 3;
    const int bm   = blockIdx.y * 128, bn = blockIdx.x * 128;

    const int ldr = tid >> 3;
    const int ldc = (tid & 7) * 4;

    const uint32_t sbase = smem_to_u32(sm);
    const int NS = K / 32;

    float acc[4][4][4];
#pragma unroll
    for (int i = 0; i < 4; i++)
#pragma unroll
        for (int j = 0; j < 4; j++)
#pragma unroll
            for (int r = 0; r < 4; r++) acc[i][j][r] = 0.f;

    auto loadTiles = [&](int k0, int buf) {
#pragma unroll
        for (int v = 0; v < 4; v++) {
            int row = ldr + v * 32;
            uint32_t sa = sbase + (uint32_t)(buf * SM_STRIDE + row * GPAD + ldc) * 4;
            cp16(sa, A + (size_t)(bm + row) * K + k0 + ldc);
            uint32_t sb = sbase + (uint32_t)(2 * SM_STRIDE + buf * SM_STRIDE + row * GPAD + ldc) * 4;
            cp16(sb, B + (size_t)(bn + row) * K + k0 + ldc);
        }
        asm volatile("cp.async.commit_group;" ::: "memory");
    };

    loadTiles(0, 0);

    for (int s = 0; s < NS; s++) {
        const int buf = s & 1;
        if (s + 1 < NS) {
            loadTiles((s + 1) * 32, buf ^ 1);
            asm volatile("cp.async.wait_group 1;" ::: "memory");
        } else {
            asm volatile("cp.async.wait_group 0;" ::: "memory");
        }
        __syncthreads();

        const float* As_ = sm + buf * SM_STRIDE;
        const float* Bs_ = sm + 2 * SM_STRIDE + buf * SM_STRIDE;

#pragma unroll
        for (int ks = 0; ks < 4; ks++) {
            uint32_t a[4][4], b[4][2];
#pragma unroll
            for (int i = 0; i < 4; i++) {
                const float* ap = As_ + (wm + i * 16 + gr) * GPAD + ks * 8 + tc;
                a[i][0] = utf32(ap[0]);
                a[i][1] = utf32(ap[8 * GPAD]);
                a[i][2] = utf32(ap[4]);
                a[i][3] = utf32(ap[8 * GPAD + 4]);
            }
#pragma unroll
            for (int j = 0; j < 4; j++) {
                const float* bp = Bs_ + (wn + j * 8 + gr) * GPAD + ks * 8 + tc;
                b[j][0] = utf32(bp[0]);
                b[j][1] = utf32(bp[4]);
            }
#pragma unroll
            for (int i = 0; i < 4; i++)
#pragma unroll
                for (int j = 0; j < 4; j++)
                    mma8(acc[i][j], a[i], b[j]);
        }
        __syncthreads();
    }

#pragma unroll
    for (int i = 0; i < 4; i++) {
#pragma unroll
        for (int j = 0; j < 4; j++) {
            int r = bm + wm + i * 16 + gr;
            int c = bn + wn + j * 8 + tc * 2;
            float2 v0 = make_float2(acc[i][j][0], acc[i][j][1]);
            float2 v1 = make_float2(acc[i][j][2], acc[i][j][3]);
            *(float2*)&C[(size_t)r * N + c]       = v0;
            *(float2*)&C[(size_t)(r + 8) * N + c] = v1;
        }
    }
}

// ===========================================================================
// RoPE + clamp (in-place on g_qkv)
// ===========================================================================
__global__ __launch_bounds__(256)
void rope_clamp_kernel()
{
    const int t = blockIdx.y;
    const int p = blockIdx.x * blockDim.x + threadIdx.x;
    float* row = g_qkv + (size_t)t * QKV_N;

    if (p < 3584) {
        int col, i;
        if (p < 3072) { col = 2 * p;               i = p & 63; }
        else          { int pp = p - 3072; col = KV_OFF + 2 * pp; i = pp & 63; }
        float a = row[col];
        float b = row[col + 1];
        float inv = (float)pow(500000.0, -(double)i / 64.0);
        float f = (float)t * inv;
        float s, c;
        sincosf(f, &s, &c);
        float a2 = a * c - b * s;
        float b2 = a * s + b * c;
        row[col]     = fminf(fmaxf(a2, -CLAMP_V), CLAMP_V);
        row[col + 1] = fminf(fmaxf(b2, -CLAMP_V), CLAMP_V);
    } else {
        int pp  = p - 3584;
        int col = V_OFF + 2 * pp;
        row[col]     = fminf(fmaxf(row[col],     -CLAMP_V), CLAMP_V);
        row[col + 1] = fminf(fmaxf(row[col + 1], -CLAMP_V), CLAMP_V);
    }
}

// ===========================================================================
// Tensor-core flash attention.
// Block: 128 q rows x 1 head; 256 threads (8 warps). KV tiles of 64.
// S = QK^T via bf16x3 (hi/lo split, 3 cross terms)  [~fp32 accurate]
// P,V rna-tf32; PV via tf32 mma with P hi/lo split (2 terms)
// ===========================================================================
// smem byte offsets (210432 total)
#define A_QH   0        // bf16 [128][136]  (34816)
#define A_QL   34816    // bf16 [128][136]
#define A_KH   69632    // bf16 [64][136]   (17408)
#define A_KL   87040    // bf16 [64][136]
#define A_VT   104448   // f32  [128][68]   (34816)
#define A_VS   139264   // f32  [64*133]    (34048)  -- aliases PH
#define A_PH   139264   // f32  [128][68]   (34816)
#define A_SS   174080   // f32  [128][68]   (34816)  -- aliases PL
#define A_PL   174080
#define A_STAT 208896   // rowM/rowL/rowA [128] each (1536)
#define ATT_SMEM 210432

__global__ __launch_bounds__(256, 1)
void attn_mma_kernel(float* __restrict__ out)
{
    extern __shared__ char smem[];
    uint32_t* QHw = (uint32_t*)(smem + A_QH);   // pitch 68 words
    uint32_t* QLw = (uint32_t*)(smem + A_QL);
    uint32_t* KHw = (uint32_t*)(smem + A_KH);
    uint32_t* KLw = (uint32_t*)(smem + A_KL);
    float*    VT  = (float*)(smem + A_VT);      // pitch 68
    float*    VS  = (float*)(smem + A_VS);      // pitch 133
    float*    PH  = (float*)(smem + A_PH);      // pitch 68
    float*    SS  = (float*)(smem + A_SS);      // pitch 68
    float*    PL  = SS;                          // alias
    float* rowM = (float*)(smem + A_STAT);
    float* rowL = rowM + 128;
    float* rowA = rowL + 128;

    const int qb   = gridDim.x - 1 - blockIdx.x;   // big tiles first
    const int h    = blockIdx.y;
    const int kh   = h / REP;
    const int tid  = threadIdx.x;
    const int wid  = tid >> 5, lane = tid & 31;
    const int gr   = lane >> 2, tc = lane & 3;
    const int m0   = (wid >> 1) * 32;              // warp q-row offset
    const int wn   = (wid & 1) * 32;               // S col offset
    const int nv   = (wid & 1) * 64;               // O col offset
    const float scale = 0.088388347648318447f;     // 1/sqrt(128)

    // ---- Load + split Q (128 x 128) ----
    {
        const float* qg = g_qkv + (size_t)(qb * 128) * QKV_N + h * HD;
#pragma unroll
        for (int i = 0; i < 16; i++) {
            int f = tid + i * 256;
            int r = f >> 5;
            int c = (f & 31) * 4;
            float4 v = *(const float4*)(qg + (size_t)r * QKV_N + c);
            uint32_t l0, l1;
            uint32_t h0 = packsplit(v.x, v.y, l0);
            uint32_t h1 = packsplit(v.z, v.w, l1);
            QHw[r * 68 + c / 2]     = h0;
            QHw[r * 68 + c / 2 + 1] = h1;
            QLw[r * 68 + c / 2]     = l0;
            QLw[r * 68 + c / 2 + 1] = l1;
        }
    }
    if (tid < 128) { rowM[tid] = -1e30f; rowL[tid] = 0.f; }

    float o[2][8][4];
#pragma unroll
    for (int mi = 0; mi < 2; mi++)
#pragma unroll
        for (int j = 0; j < 8; j++)
#pragma unroll
            for (int r = 0; r < 4; r++) o[mi][j][r] = 0.f;

    const int nkt = 2 * qb + 2;
    for (int kt = 0; kt < nkt; kt++) {
        __syncthreads();   // prev PV done before clobbering K / VS(=PH)

        // ---- Load K (split) + V (stage) ----
        {
            const float* kg = g_qkv + (size_t)(kt * 64) * QKV_N + KV_OFF + kh * HD;
            const float* vg = g_qkv + (size_t)(kt * 64) * QKV_N + V_OFF  + kh * HD;
#pragma unroll
            for (int i = 0; i < 8; i++) {
                int f = tid + i * 256;
                int r = f >> 5;
                int c = (f & 31) * 4;
                float4 kv = *(const float4*)(kg + (size_t)r * QKV_N + c);
                uint32_t l0, l1;
                uint32_t h0 = packsplit(kv.x, kv.y, l0);
                uint32_t h1 = packsplit(kv.z, kv.w, l1);
                KHw[r * 68 + c / 2]     = h0;
                KHw[r * 68 + c / 2 + 1] = h1;
                KLw[r * 68 + c / 2]     = l0;
                KLw[r * 68 + c / 2 + 1] = l1;
                float4 vv = *(const float4*)(vg + (size_t)r * QKV_N + c);
                VS[r * 133 + c + 0] = vv.x;
                VS[r * 133 + c + 1] = vv.y;
                VS[r * 133 + c + 2] = vv.z;
                VS[r * 133 + c + 3] = vv.w;
            }
        }
        __syncthreads();

        // ---- Transpose V: VS[64][133] -> VT[128][68] (rna-tf32) ----
#pragma unroll
        for (int i = 0; i < 32; i++) {
            int widx = wid + 8 * i;          // 0..255
            int d = widx >> 1;
            int r = (widx & 1) * 32 + lane;
            VT[d * 68 + r] = ftf32(VS[r * 133 + d]);
        }

        // ---- S = Q K^T (bf16x3) ----
        float sacc[2][4][4];
#pragma unroll
        for (int mi = 0; mi < 2; mi++)
#pragma unroll
            for (int j = 0; j < 4; j++)
#pragma unroll
                for (int r = 0; r < 4; r++) sacc[mi][j][r] = 0.f;

#pragma unroll
        for (int ks = 0; ks < 8; ks++) {
            uint32_t ah[2][4], al[2][4];
#pragma unroll
            for (int mi = 0; mi < 2; mi++) {
                int base = (m0 + mi * 16 + gr) * 68 + ks * 8 + tc;
                ah[mi][0] = QHw[base];
                ah[mi][1] = QHw[base + 8 * 68];
                ah[mi][2] = QHw[base + 4];
                ah[mi][3] = QHw[base + 8 * 68 + 4];
                al[mi][0] = QLw[base];
                al[mi][1] = QLw[base + 8 * 68];
                al[mi][2] = QLw[base + 4];
                al[mi][3] = QLw[base + 8 * 68 + 4];
            }
            uint32_t bh[4][2], bl[4][2];
#pragma unroll
            for (int j = 0; j < 4; j++) {
                int base = (wn + j * 8 + gr) * 68 + ks * 8 + tc;
                bh[j][0] = KHw[base];
                bh[j][1] = KHw[base + 4];
                bl[j][0] = KLw[base];
                bl[j][1] = KLw[base + 4];
            }
#pragma unroll
            for (int mi = 0; mi < 2; mi++)
#pragma unroll
                for (int j = 0; j < 4; j++) {
                    mma16bf(sacc[mi][j], ah[mi], bh[j]);
                    mma16bf(sacc[mi][j], ah[mi], bl[j]);
                    mma16bf(sacc[mi][j], al[mi], bh[j]);
                }
        }

        // ---- scale + causal mask + store S ----
        const bool dg = (kt >= 2 * qb);
#pragma unroll
        for (int mi = 0; mi < 2; mi++) {
#pragma unroll
            for (int j = 0; j < 4; j++) {
                int rl0 = m0 + mi * 16 + gr;
                int cl  = wn + j * 8 + 2 * tc;
                float v0 = sacc[mi][j][0] * scale;
                float v1 = sacc[mi][j][1] * scale;
                float v2 = sacc[mi][j][2] * scale;
                float v3 = sacc[mi][j][3] * scale;
                if (dg) {
                    int rg0 = qb * 128 + rl0;
                    int cg  = kt * 64 + cl;
                    if (cg     > rg0)     v0 = -1e30f;
                    if (cg + 1 > rg0)     v1 = -1e30f;
                    if (cg     > rg0 + 8) v2 = -1e30f;
                    if (cg + 1 > rg0 + 8) v3 = -1e30f;
                }
                *(float2*)&SS[rl0 * 68 + cl]       = make_float2(v0, v1);
                *(float2*)&SS[(rl0 + 8) * 68 + cl] = make_float2(v2, v3);
            }
        }
        __syncthreads();

        // ---- online softmax (128 threads, one row each); write Ph/Pl ----
        if (tid < 128) {
            int r = tid;
            float mOld = rowM[r];
            float m = mOld;
            const float4* srow = (const float4*)(SS + r * 68);
#pragma unroll
            for (int jj = 0; jj < 16; jj++) {
                float4 s4 = srow[jj];
                m = fmaxf(m, fmaxf(fmaxf(s4.x, s4.y), fmaxf(s4.z, s4.w)));
            }
            float alpha = __expf(mOld - m);
            float l = 0.f;
#pragma unroll
            for (int jj = 0; jj < 16; jj++) {
                float4 s4 = srow[jj];
                float p0 = __expf(s4.x - m);
                float p1 = __expf(s4.y - m);
                float p2 = __expf(s4.z - m);
                float p3 = __expf(s4.w - m);
                l += (p0 + p1) + (p2 + p3);
                float h0 = ftf32(p0), h1 = ftf32(p1), h2 = ftf32(p2), h3 = ftf32(p3);
                float4 hv = make_float4(h0, h1, h2, h3);
                float4 lv = make_float4(ftf32(p0 - h0), ftf32(p1 - h1),
                                        ftf32(p2 - h2), ftf32(p3 - h3));
                *(float4*)&PH[r * 68 + jj * 4] = hv;
                *(float4*)&PL[r * 68 + jj * 4] = lv;   // overwrites SS after read
            }
            rowL[r] = rowL[r] * alpha + l;
            rowM[r] = m;
            rowA[r] = alpha;
        }
        __syncthreads();

        // ---- O = alpha*O + P V  (tf32, P split) ----
#pragma unroll
        for (int mi = 0; mi < 2; mi++) {
            float am0 = rowA[m0 + mi * 16 + gr];
            float am1 = rowA[m0 + mi * 16 + gr + 8];
#pragma unroll
            for (int j = 0; j < 8; j++) {
                o[mi][j][0] *= am0; o[mi][j][1] *= am0;
                o[mi][j][2] *= am1; o[mi][j][3] *= am1;
            }
        }
#pragma unroll
        for (int ks = 0; ks < 8; ks++) {
            uint32_t ap[2][4], alr[2][4];
#pragma unroll
            for (int mi = 0; mi < 2; mi++) {
                int base = (m0 + mi * 16 + gr) * 68 + ks * 8 + tc;
                ap[mi][0]  = __float_as_uint(PH[base]);
                ap[mi][1]  = __float_as_uint(PH[base + 8 * 68]);
                ap[mi][2]  = __float_as_uint(PH[base + 4]);
                ap[mi][3]  = __float_as_uint(PH[base + 8 * 68 + 4]);
                alr[mi][0] = __float_as_uint(PL[base]);
                alr[mi][1] = __float_as_uint(PL[base + 8 * 68]);
                alr[mi][2] = __float_as_uint(PL[base + 4]);
                alr[mi][3] = __float_as_uint(PL[base + 8 * 68 + 4]);
            }
#pragma unroll
            for (int j = 0; j < 8; j++) {
                int base = (nv + j * 8 + gr) * 68 + ks * 8 + tc;
                uint32_t b[2];
                b[0] = __float_as_uint(VT[base]);
                b[1] = __float_as_uint(VT[base + 4]);
#pragma unroll
                for (int mi = 0; mi < 2; mi++) {
                    mma8(o[mi][j], ap[mi], b);
                    mma8(o[mi][j], alr[mi], b);
                }
            }
        }
    }

    // ---- normalize + store ----
#pragma unroll
    for (int mi = 0; mi < 2; mi++) {
        int rl0 = m0 + mi * 16 + gr;
        float inv0 = 1.f / rowL[rl0];
        float inv1 = 1.f / rowL[rl0 + 8];
        int rg0 = qb * 128 + rl0;
#pragma unroll
        for (int j = 0; j < 8; j++) {
            int col = h * HD + nv + j * 8 + 2 * tc;
            *(float2*)&out[(size_t)rg0 * DM + col] =
                make_float2(o[mi][j][0] * inv0, o[mi][j][1] * inv0);
            *(float2*)&out[(size_t)(rg0 + 8) * DM + col] =
                make_float2(o[mi][j][2] * inv1, o[mi][j][3] * inv1);
        }
    }
}

// ===========================================================================
// Host side
// ===========================================================================
extern "C" void kernel_launch(void* const* d_in, const int* in_sizes, int n_in,
                              void* d_out, int out_size)
{
    const float* x     = (const float*)d_in[0];
    const float* w_qkv = (const float*)d_in[2];
    const float* w_out = (const float*)d_in[3];
    float* out = (float*)d_out;

    float *qkv, *attn;
    cudaGetSymbolAddress((void**)&qkv,  g_qkv);
    cudaGetSymbolAddress((void**)&attn, g_attn);

    cudaFuncSetAttribute(gemm_mma, cudaFuncAttributeMaxDynamicSharedMemorySize,
                         GEMM_SMEM_BYTES);
    cudaFuncSetAttribute(attn_mma_kernel, cudaFuncAttributeMaxDynamicSharedMemorySize,
                         ATT_SMEM);

    // 1) QKV projection (tf32 mma, rna rounding in-register)
    {
        dim3 grid(QKV_N / 128, TT / 128);
        gemm_mma<<<grid, 256, GEMM_SMEM_BYTES>>>(x, w_qkv, qkv, QKV_N, DM);
    }

    // 2) RoPE + clamp
    {
        dim3 grid(16, TT);
        rope_clamp_kernel<<<grid, 256>>>();
    }

    // 3) Tensor-core flash attention
    {
        dim3 grid(TT / 128, NH);
        attn_mma_kernel<<<grid, 256, ATT_SMEM>>>(attn);
    }

    // 4) Output projection
    {
        dim3 grid(DM / 128, TT / 128);
        gemm_mma<<<grid, 256, GEMM_SMEM_BYTES>>>(attn, w_out, out, DM, DM);
    }
}

// round 5
// speedup vs baseline: 4.2845x; 1.3464x over previous
#include <cuda_runtime.h>
#include <cuda_bf16.h>
#include <math.h>
#include <stdint.h>

// Problem constants
#define TT      2048
#define DM      6144
#define NH      48
#define NKV     8
#define HD      128
#define QKV_N   8192
#define KV_OFF  DM
#define V_OFF   (DM + NKV*HD)
#define REP     (NH / NKV)
#define CLAMP_V 8.0f

// Scratch
__device__ float g_qkv[(size_t)TT * QKV_N];     // 64 MB
__device__ float g_attn[(size_t)TT * DM];       // 48 MB

// ===========================================================================
// Helpers
// ===========================================================================
__device__ __forceinline__ uint32_t smem_to_u32(const void* p) {
    uint32_t a;
    asm("{ .reg .u64 t; cvta.to.shared.u64 t, %1; cvt.u32.u64 %0, t; }"
        : "=r"(a) : "l"(p));
    return a;
}
__device__ __forceinline__ void cp16(uint32_t s, const void* g) {
    asm volatile("cp.async.cg.shared.global [%0], [%1], 16;"
                 :: "r"(s), "l"(g) : "memory");
}
__device__ __forceinline__ float ftf32(float x) {
    uint32_t o, i = __float_as_uint(x);
    asm("cvt.rna.tf32.f32 %0, %1;" : "=r"(o) : "r"(i));
    return __uint_as_float(o);
}
__device__ __forceinline__ uint32_t utf32(float x) {
    uint32_t o, i = __float_as_uint(x);
    asm("cvt.rna.tf32.f32 %0, %1;" : "=r"(o) : "r"(i));
    return o;
}
// tf32 m16n8k8 mma
__device__ __forceinline__ void mma8(float* d, const uint32_t* a, const uint32_t* b) {
    asm volatile(
        "mma.sync.aligned.m16n8k8.row.col.f32.tf32.tf32.f32 "
        "{%0,%1,%2,%3}, {%4,%5,%6,%7}, {%8,%9}, {%0,%1,%2,%3};"
        : "+f"(d[0]), "+f"(d[1]), "+f"(d[2]), "+f"(d[3])
        : "r"(a[0]), "r"(a[1]), "r"(a[2]), "r"(a[3]), "r"(b[0]), "r"(b[1]));
}
// bf16 m16n8k16 mma
__device__ __forceinline__ void mma16bf(float* d, const uint32_t* a, const uint32_t* b) {
    asm volatile(
        "mma.sync.aligned.m16n8k16.row.col.f32.bf16.bf16.f32 "
        "{%0,%1,%2,%3}, {%4,%5,%6,%7}, {%8,%9}, {%0,%1,%2,%3};"
        : "+f"(d[0]), "+f"(d[1]), "+f"(d[2]), "+f"(d[3])
        : "r"(a[0]), "r"(a[1]), "r"(a[2]), "r"(a[3]), "r"(b[0]), "r"(b[1]));
}
// split (x,y) into packed bf16x2 hi word (ret) + lo word
__device__ __forceinline__ uint32_t packsplit(float x, float y, uint32_t& lo) {
    __nv_bfloat16 hx = __float2bfloat16(x);
    __nv_bfloat16 hy = __float2bfloat16(y);
    float rx = x - __bfloat162float(hx);
    float ry = y - __bfloat162float(hy);
    __nv_bfloat16 lx = __float2bfloat16(rx);
    __nv_bfloat16 ly = __float2bfloat16(ry);
    lo = ((uint32_t)__bfloat16_as_ushort(ly) << 16) | __bfloat16_as_ushort(lx);
    return ((uint32_t)__bfloat16_as_ushort(hy) << 16) | __bfloat16_as_ushort(hx);
}
__device__ __forceinline__ float clmp(float v) {
    return fminf(fmaxf(v, -CLAMP_V), CLAMP_V);
}

// ===========================================================================
// tf32 mma.sync GEMM: C[M,N] = A[M,K] * B[N,K]^T  (raw fp32 in, rna-tf32 in-reg)
// mode 0: plain store.  mode 1: fused RoPE+clamp epilogue (QKV projection).
// 2 CTAs/SM (regs capped at 128), double-buffered cp.async, BK=32.
// ===========================================================================
#define GPAD 36
#define SM_STRIDE (128 * GPAD)
#define GEMM_SMEM_BYTES (4 * SM_STRIDE * 4)

__global__ __launch_bounds__(256, 2)
void gemm_mma(const float* __restrict__ A, const float* __restrict__ B,
              float* __restrict__ C, int N, int K, int mode)
{
    extern __shared__ float sm[];
    const int tid  = threadIdx.x;
    const int wid  = tid >> 5, lane = tid & 31;
    const int wm   = (wid >> 2) * 64;
    const int wn   = (wid & 3) * 32;
    const int gr   = lane >> 2, tc = lane & 3;
    const int bm   = blockIdx.y * 128, bn = blockIdx.x * 128;

    const int ldr = tid >> 3;
    const int ldc = (tid & 7) * 4;

    const uint32_t sbase = smem_to_u32(sm);
    const int NS = K / 32;

    float acc[4][4][4];
#pragma unroll
    for (int i = 0; i < 4; i++)
#pragma unroll
        for (int j = 0; j < 4; j++)
#pragma unroll
            for (int r = 0; r < 4; r++) acc[i][j][r] = 0.f;

    auto loadTiles = [&](int k0, int buf) {
#pragma unroll
        for (int v = 0; v < 4; v++) {
            int row = ldr + v * 32;
            uint32_t sa = sbase + (uint32_t)(buf * SM_STRIDE + row * GPAD + ldc) * 4;
            cp16(sa, A + (size_t)(bm + row) * K + k0 + ldc);
            uint32_t sb = sbase + (uint32_t)(2 * SM_STRIDE + buf * SM_STRIDE + row * GPAD + ldc) * 4;
            cp16(sb, B + (size_t)(bn + row) * K + k0 + ldc);
        }
        asm volatile("cp.async.commit_group;" ::: "memory");
    };

    loadTiles(0, 0);

    for (int s = 0; s < NS; s++) {
        const int buf = s & 1;
        if (s + 1 < NS) {
            loadTiles((s + 1) * 32, buf ^ 1);
            asm volatile("cp.async.wait_group 1;" ::: "memory");
        } else {
            asm volatile("cp.async.wait_group 0;" ::: "memory");
        }
        __syncthreads();

        const float* As_ = sm + buf * SM_STRIDE;
        const float* Bs_ = sm + 2 * SM_STRIDE + buf * SM_STRIDE;

#pragma unroll
        for (int ks = 0; ks < 4; ks++) {
            uint32_t a[4][4], b[4][2];
#pragma unroll
            for (int i = 0; i < 4; i++) {
                const float* ap = As_ + (wm + i * 16 + gr) * GPAD + ks * 8 + tc;
                a[i][0] = utf32(ap[0]);
                a[i][1] = utf32(ap[8 * GPAD]);
                a[i][2] = utf32(ap[4]);
                a[i][3] = utf32(ap[8 * GPAD + 4]);
            }
#pragma unroll
            for (int j = 0; j < 4; j++) {
                const float* bp = Bs_ + (wn + j * 8 + gr) * GPAD + ks * 8 + tc;
                b[j][0] = utf32(bp[0]);
                b[j][1] = utf32(bp[4]);
            }
#pragma unroll
            for (int i = 0; i < 4; i++)
#pragma unroll
                for (int j = 0; j < 4; j++)
                    mma8(acc[i][j], a[i], b[j]);
        }
        __syncthreads();
    }

    // Epilogue. Pairs (c, c+1) per float2 store == RoPE pairs when mode==1.
#pragma unroll
    for (int i = 0; i < 4; i++) {
#pragma unroll
        for (int j = 0; j < 4; j++) {
            int r = bm + wm + i * 16 + gr;
            int c = bn + wn + j * 8 + tc * 2;
            float2 v0 = make_float2(acc[i][j][0], acc[i][j][1]);
            float2 v1 = make_float2(acc[i][j][2], acc[i][j][3]);
            if (mode == 1) {
                if (c < V_OFF) {
                    // RoPE pair: i64 = pair index within head (Q and K sections)
                    int i64 = (c >> 1) & 63;
                    float inv = (float)pow(500000.0, -(double)i64 / 64.0);
                    float s0, c0;
                    sincosf((float)r * inv, &s0, &c0);
                    float a0 = v0.x, b0 = v0.y;
                    v0.x = clmp(a0 * c0 - b0 * s0);
                    v0.y = clmp(a0 * s0 + b0 * c0);
                    float s1, c1;
                    sincosf((float)(r + 8) * inv, &s1, &c1);
                    float a1 = v1.x, b1 = v1.y;
                    v1.x = clmp(a1 * c1 - b1 * s1);
                    v1.y = clmp(a1 * s1 + b1 * c1);
                } else {
                    v0.x = clmp(v0.x); v0.y = clmp(v0.y);
                    v1.x = clmp(v1.x); v1.y = clmp(v1.y);
                }
            }
            *(float2*)&C[(size_t)r * N + c]       = v0;
            *(float2*)&C[(size_t)(r + 8) * N + c] = v1;
        }
    }
}

// ===========================================================================
// Tensor-core flash attention (unchanged from R4).
// ===========================================================================
#define A_QH   0
#define A_QL   34816
#define A_KH   69632
#define A_KL   87040
#define A_VT   104448
#define A_VS   139264
#define A_PH   139264
#define A_SS   174080
#define A_PL   174080
#define A_STAT 208896
#define ATT_SMEM 210432

__global__ __launch_bounds__(256, 1)
void attn_mma_kernel(float* __restrict__ out)
{
    extern __shared__ char smem[];
    uint32_t* QHw = (uint32_t*)(smem + A_QH);
    uint32_t* QLw = (uint32_t*)(smem + A_QL);
    uint32_t* KHw = (uint32_t*)(smem + A_KH);
    uint32_t* KLw = (uint32_t*)(smem + A_KL);
    float*    VT  = (float*)(smem + A_VT);
    float*    VS  = (float*)(smem + A_VS);
    float*    PH  = (float*)(smem + A_PH);
    float*    SS  = (float*)(smem + A_SS);
    float*    PL  = SS;
    float* rowM = (float*)(smem + A_STAT);
    float* rowL = rowM + 128;
    float* rowA = rowL + 128;

    const int qb   = gridDim.x - 1 - blockIdx.x;
    const int h    = blockIdx.y;
    const int kh   = h / REP;
    const int tid  = threadIdx.x;
    const int wid  = tid >> 5, lane = tid & 31;
    const int gr   = lane >> 2, tc = lane & 3;
    const int m0   = (wid >> 1) * 32;
    const int wn   = (wid & 1) * 32;
    const int nv   = (wid & 1) * 64;
    const float scale = 0.088388347648318447f;

    {
        const float* qg = g_qkv + (size_t)(qb * 128) * QKV_N + h * HD;
#pragma unroll
        for (int i = 0; i < 16; i++) {
            int f = tid + i * 256;
            int r = f >> 5;
            int c = (f & 31) * 4;
            float4 v = *(const float4*)(qg + (size_t)r * QKV_N + c);
            uint32_t l0, l1;
            uint32_t h0 = packsplit(v.x, v.y, l0);
            uint32_t h1 = packsplit(v.z, v.w, l1);
            QHw[r * 68 + c / 2]     = h0;
            QHw[r * 68 + c / 2 + 1] = h1;
            QLw[r * 68 + c / 2]     = l0;
            QLw[r * 68 + c / 2 + 1] = l1;
        }
    }
    if (tid < 128) { rowM[tid] = -1e30f; rowL[tid] = 0.f; }

    float o[2][8][4];
#pragma unroll
    for (int mi = 0; mi < 2; mi++)
#pragma unroll
        for (int j = 0; j < 8; j++)
#pragma unroll
            for (int r = 0; r < 4; r++) o[mi][j][r] = 0.f;

    const int nkt = 2 * qb + 2;
    for (int kt = 0; kt < nkt; kt++) {
        __syncthreads();

        {
            const float* kg = g_qkv + (size_t)(kt * 64) * QKV_N + KV_OFF + kh * HD;
            const float* vg = g_qkv + (size_t)(kt * 64) * QKV_N + V_OFF  + kh * HD;
#pragma unroll
            for (int i = 0; i < 8; i++) {
                int f = tid + i * 256;
                int r = f >> 5;
                int c = (f & 31) * 4;
                float4 kv = *(const float4*)(kg + (size_t)r * QKV_N + c);
                uint32_t l0, l1;
                uint32_t h0 = packsplit(kv.x, kv.y, l0);
                uint32_t h1 = packsplit(kv.z, kv.w, l1);
                KHw[r * 68 + c / 2]     = h0;
                KHw[r * 68 + c / 2 + 1] = h1;
                KLw[r * 68 + c / 2]     = l0;
                KLw[r * 68 + c / 2 + 1] = l1;
                float4 vv = *(const float4*)(vg + (size_t)r * QKV_N + c);
                VS[r * 133 + c + 0] = vv.x;
                VS[r * 133 + c + 1] = vv.y;
                VS[r * 133 + c + 2] = vv.z;
                VS[r * 133 + c + 3] = vv.w;
            }
        }
        __syncthreads();

#pragma unroll
        for (int i = 0; i < 32; i++) {
            int widx = wid + 8 * i;
            int d = widx >> 1;
            int r = (widx & 1) * 32 + lane;
            VT[d * 68 + r] = ftf32(VS[r * 133 + d]);
        }

        float sacc[2][4][4];
#pragma unroll
        for (int mi = 0; mi < 2; mi++)
#pragma unroll
            for (int j = 0; j < 4; j++)
#pragma unroll
                for (int r = 0; r < 4; r++) sacc[mi][j][r] = 0.f;

#pragma unroll
        for (int ks = 0; ks < 8; ks++) {
            uint32_t ah[2][4], al[2][4];
#pragma unroll
            for (int mi = 0; mi < 2; mi++) {
                int base = (m0 + mi * 16 + gr) * 68 + ks * 8 + tc;
                ah[mi][0] = QHw[base];
                ah[mi][1] = QHw[base + 8 * 68];
                ah[mi][2] = QHw[base + 4];
                ah[mi][3] = QHw[base + 8 * 68 + 4];
                al[mi][0] = QLw[base];
                al[mi][1] = QLw[base + 8 * 68];
                al[mi][2] = QLw[base + 4];
                al[mi][3] = QLw[base + 8 * 68 + 4];
            }
            uint32_t bh[4][2], bl[4][2];
#pragma unroll
            for (int j = 0; j < 4; j++) {
                int base = (wn + j * 8 + gr) * 68 + ks * 8 + tc;
                bh[j][0] = KHw[base];
                bh[j][1] = KHw[base + 4];
                bl[j][0] = KLw[base];
                bl[j][1] = KLw[base + 4];
            }
#pragma unroll
            for (int mi = 0; mi < 2; mi++)
#pragma unroll
                for (int j = 0; j < 4; j++) {
                    mma16bf(sacc[mi][j], ah[mi], bh[j]);
                    mma16bf(sacc[mi][j], ah[mi], bl[j]);
                    mma16bf(sacc[mi][j], al[mi], bh[j]);
                }
        }

        const bool dg = (kt >= 2 * qb);
#pragma unroll
        for (int mi = 0; mi < 2; mi++) {
#pragma unroll
            for (int j = 0; j < 4; j++) {
                int rl0 = m0 + mi * 16 + gr;
                int cl  = wn + j * 8 + 2 * tc;
                float v0 = sacc[mi][j][0] * scale;
                float v1 = sacc[mi][j][1] * scale;
                float v2 = sacc[mi][j][2] * scale;
                float v3 = sacc[mi][j][3] * scale;
                if (dg) {
                    int rg0 = qb * 128 + rl0;
                    int cg  = kt * 64 + cl;
                    if (cg     > rg0)     v0 = -1e30f;
                    if (cg + 1 > rg0)     v1 = -1e30f;
                    if (cg     > rg0 + 8) v2 = -1e30f;
                    if (cg + 1 > rg0 + 8) v3 = -1e30f;
                }
                *(float2*)&SS[rl0 * 68 + cl]       = make_float2(v0, v1);
                *(float2*)&SS[(rl0 + 8) * 68 + cl] = make_float2(v2, v3);
            }
        }
        __syncthreads();

        if (tid < 128) {
            int r = tid;
            float mOld = rowM[r];
            float m = mOld;
            const float4* srow = (const float4*)(SS + r * 68);
#pragma unroll
            for (int jj = 0; jj < 16; jj++) {
                float4 s4 = srow[jj];
                m = fmaxf(m, fmaxf(fmaxf(s4.x, s4.y), fmaxf(s4.z, s4.w)));
            }
            float alpha = __expf(mOld - m);
            float l = 0.f;
#pragma unroll
            for (int jj = 0; jj < 16; jj++) {
                float4 s4 = srow[jj];
                float p0 = __expf(s4.x - m);
                float p1 = __expf(s4.y - m);
                float p2 = __expf(s4.z - m);
                float p3 = __expf(s4.w - m);
                l += (p0 + p1) + (p2 + p3);
                float h0 = ftf32(p0), h1 = ftf32(p1), h2 = ftf32(p2), h3 = ftf32(p3);
                float4 hv = make_float4(h0, h1, h2, h3);
                float4 lv = make_float4(ftf32(p0 - h0), ftf32(p1 - h1),
                                        ftf32(p2 - h2), ftf32(p3 - h3));
                *(float4*)&PH[r * 68 + jj * 4] = hv;
                *(float4*)&PL[r * 68 + jj * 4] = lv;
            }
            rowL[r] = rowL[r] * alpha + l;
            rowM[r] = m;
            rowA[r] = alpha;
        }
        __syncthreads();

#pragma unroll
        for (int mi = 0; mi < 2; mi++) {
            float am0 = rowA[m0 + mi * 16 + gr];
            float am1 = rowA[m0 + mi * 16 + gr + 8];
#pragma unroll
            for (int j = 0; j < 8; j++) {
                o[mi][j][0] *= am0; o[mi][j][1] *= am0;
                o[mi][j][2] *= am1; o[mi][j][3] *= am1;
            }
        }
#pragma unroll
        for (int ks = 0; ks < 8; ks++) {
            uint32_t ap[2][4], alr[2][4];
#pragma unroll
            for (int mi = 0; mi < 2; mi++) {
                int base = (m0 + mi * 16 + gr) * 68 + ks * 8 + tc;
                ap[mi][0]  = __float_as_uint(PH[base]);
                ap[mi][1]  = __float_as_uint(PH[base + 8 * 68]);
                ap[mi][2]  = __float_as_uint(PH[base + 4]);
                ap[mi][3]  = __float_as_uint(PH[base + 8 * 68 + 4]);
                alr[mi][0] = __float_as_uint(PL[base]);
                alr[mi][1] = __float_as_uint(PL[base + 8 * 68]);
                alr[mi][2] = __float_as_uint(PL[base + 4]);
                alr[mi][3] = __float_as_uint(PL[base + 8 * 68 + 4]);
            }
#pragma unroll
            for (int j = 0; j < 8; j++) {
                int base = (nv + j * 8 + gr) * 68 + ks * 8 + tc;
                uint32_t b[2];
                b[0] = __float_as_uint(VT[base]);
                b[1] = __float_as_uint(VT[base + 4]);
#pragma unroll
                for (int mi = 0; mi < 2; mi++) {
                    mma8(o[mi][j], ap[mi], b);
                    mma8(o[mi][j], alr[mi], b);
                }
            }
        }
    }

#pragma unroll
    for (int mi = 0; mi < 2; mi++) {
        int rl0 = m0 + mi * 16 + gr;
        float inv0 = 1.f / rowL[rl0];
        float inv1 = 1.f / rowL[rl0 + 8];
        int rg0 = qb * 128 + rl0;
#pragma unroll
        for (int j = 0; j < 8; j++) {
            int col = h * HD + nv + j * 8 + 2 * tc;
            *(float2*)&out[(size_t)rg0 * DM + col] =
                make_float2(o[mi][j][0] * inv0, o[mi][j][1] * inv0);
            *(float2*)&out[(size_t)(rg0 + 8) * DM + col] =
                make_float2(o[mi][j][2] * inv1, o[mi][j][3] * inv1);
        }
    }
}

// ===========================================================================
// Host side
// ===========================================================================
extern "C" void kernel_launch(void* const* d_in, const int* in_sizes, int n_in,
                              void* d_out, int out_size)
{
    const float* x     = (const float*)d_in[0];
    const float* w_qkv = (const float*)d_in[2];
    const float* w_out = (const float*)d_in[3];
    float* out = (float*)d_out;

    float *qkv, *attn;
    cudaGetSymbolAddress((void**)&qkv,  g_qkv);
    cudaGetSymbolAddress((void**)&attn, g_attn);

    cudaFuncSetAttribute(gemm_mma, cudaFuncAttributeMaxDynamicSharedMemorySize,
                         GEMM_SMEM_BYTES);
    cudaFuncSetAttribute(attn_mma_kernel, cudaFuncAttributeMaxDynamicSharedMemorySize,
                         ATT_SMEM);

    // 1) QKV projection + fused RoPE/clamp epilogue
    {
        dim3 grid(QKV_N / 128, TT / 128);
        gemm_mma<<<grid, 256, GEMM_SMEM_BYTES>>>(x, w_qkv, qkv, QKV_N, DM, 1);
    }

    // 2) Tensor-core flash attention
    {
        dim3 grid(TT / 128, NH);
        attn_mma_kernel<<<grid, 256, ATT_SMEM>>>(attn);
    }

    // 3) Output projection
    {
        dim3 grid(DM / 128, TT / 128);
        gemm_mma<<<grid, 256, GEMM_SMEM_BYTES>>>(attn, w_out, out, DM, DM, 0);
    }
}

// round 6
// speedup vs baseline: 4.5531x; 1.0627x over previous
#include <cuda_runtime.h>
#include <cuda_bf16.h>
#include <math.h>
#include <stdint.h>

// Problem constants
#define TT      2048
#define DM      6144
#define NH      48
#define NKV     8
#define HD      128
#define QKV_N   8192
#define KV_OFF  DM
#define V_OFF   (DM + NKV*HD)
#define REP     (NH / NKV)
#define CLAMP_V 8.0f

// Scratch (static device globals)
__device__ float g_qkv[(size_t)TT * QKV_N];      // qkv activations (normal layout)
__device__ float g_attn[(size_t)TT * DM];        // attn out (K-permuted + tf32-rounded)
__device__ float g_xp[(size_t)TT * DM];          // perm+rna x
__device__ float g_wqkvp[(size_t)QKV_N * DM];    // perm+rna w_qkv
__device__ float g_woutp[(size_t)DM * DM];       // perm+rna w_out

// ===========================================================================
// Helpers
// ===========================================================================
__device__ __forceinline__ uint32_t smem_to_u32(const void* p) {
    uint32_t a;
    asm("{ .reg .u64 t; cvta.to.shared.u64 t, %1; cvt.u32.u64 %0, t; }"
        : "=r"(a) : "l"(p));
    return a;
}
__device__ __forceinline__ void cp16(uint32_t s, const void* g) {
    asm volatile("cp.async.cg.shared.global [%0], [%1], 16;"
                 :: "r"(s), "l"(g) : "memory");
}
__device__ __forceinline__ float ftf32(float x) {
    uint32_t o, i = __float_as_uint(x);
    asm("cvt.rna.tf32.f32 %0, %1;" : "=r"(o) : "r"(i));
    return __uint_as_float(o);
}
// tf32 m16n8k8 mma
__device__ __forceinline__ void mma8(float* d, const uint32_t* a, const uint32_t* b) {
    asm volatile(
        "mma.sync.aligned.m16n8k8.row.col.f32.tf32.tf32.f32 "
        "{%0,%1,%2,%3}, {%4,%5,%6,%7}, {%8,%9}, {%0,%1,%2,%3};"
        : "+f"(d[0]), "+f"(d[1]), "+f"(d[2]), "+f"(d[3])
        : "r"(a[0]), "r"(a[1]), "r"(a[2]), "r"(a[3]), "r"(b[0]), "r"(b[1]));
}
// bf16 m16n8k16 mma
__device__ __forceinline__ void mma16bf(float* d, const uint32_t* a, const uint32_t* b) {
    asm volatile(
        "mma.sync.aligned.m16n8k16.row.col.f32.bf16.bf16.f32 "
        "{%0,%1,%2,%3}, {%4,%5,%6,%7}, {%8,%9}, {%0,%1,%2,%3};"
        : "+f"(d[0]), "+f"(d[1]), "+f"(d[2]), "+f"(d[3])
        : "r"(a[0]), "r"(a[1]), "r"(a[2]), "r"(a[3]), "r"(b[0]), "r"(b[1]));
}
__device__ __forceinline__ uint32_t packsplit(float x, float y, uint32_t& lo) {
    __nv_bfloat16 hx = __float2bfloat16(x);
    __nv_bfloat16 hy = __float2bfloat16(y);
    float rx = x - __bfloat162float(hx);
    float ry = y - __bfloat162float(hy);
    __nv_bfloat16 lx = __float2bfloat16(rx);
    __nv_bfloat16 ly = __float2bfloat16(ry);
    lo = ((uint32_t)__bfloat16_as_ushort(ly) << 16) | __bfloat16_as_ushort(lx);
    return ((uint32_t)__bfloat16_as_ushort(hy) << 16) | __bfloat16_as_ushort(hx);
}
__device__ __forceinline__ float clmp(float v) {
    return fminf(fmaxf(v, -CLAMP_V), CLAMP_V);
}

// ===========================================================================
// Permute (within-8 interleave [0,4,1,5,2,6,3,7]) + rna-tf32 round.
// One thread per 8-column group; fully coalesced float4 I/O.
// ===========================================================================
__global__ __launch_bounds__(256)
void perm_round_kernel(const float4* __restrict__ src, float4* __restrict__ dst, int n8)
{
    int g = blockIdx.x * blockDim.x + threadIdx.x;
    if (g < n8) {
        float4 i0 = src[2 * g];       // orig cols 0..3
        float4 i1 = src[2 * g + 1];   // orig cols 4..7
        float4 o0 = make_float4(ftf32(i0.x), ftf32(i1.x), ftf32(i0.y), ftf32(i1.y));
        float4 o1 = make_float4(ftf32(i0.z), ftf32(i1.z), ftf32(i0.w), ftf32(i1.w));
        dst[2 * g]     = o0;
        dst[2 * g + 1] = o1;
    }
}

// ===========================================================================
// tf32 mma.sync GEMM on K-PERMUTED pre-rounded operands.
// C[M,N] = A[M,K] * B[N,K]^T.  Fragment pairs (k, k+4) adjacent -> LDS.64.
// mode 0: plain store.  mode 1: fused RoPE+clamp epilogue.
// ===========================================================================
#define GPAD 40
#define SM_STRIDE (128 * GPAD)
#define GEMM_SMEM_BYTES (4 * SM_STRIDE * 4)   // 81920

__global__ __launch_bounds__(256, 2)
void gemm_mma(const float* __restrict__ A, const float* __restrict__ B,
              float* __restrict__ C, int N, int K, int mode)
{
    extern __shared__ float sm[];
    const int tid  = threadIdx.x;
    const int wid  = tid >> 5, lane = tid & 31;
    const int wm   = (wid >> 2) * 64;
    const int wn   = (wid & 3) * 32;
    const int gr   = lane >> 2, tc = lane & 3;
    const int bm   = blockIdx.y * 128, bn = blockIdx.x * 128;

    const int ldr = tid >> 3;
    const int ldc = (tid & 7) * 4;

    const uint32_t sbase = smem_to_u32(sm);
    const int NS = K / 32;

    float acc[4][4][4];
#pragma unroll
    for (int i = 0; i < 4; i++)
#pragma unroll
        for (int j = 0; j < 4; j++)
#pragma unroll
            for (int r = 0; r < 4; r++) acc[i][j][r] = 0.f;

    auto loadTiles = [&](int k0, int buf) {
#pragma unroll
        for (int v = 0; v < 4; v++) {
            int row = ldr + v * 32;
            uint32_t sa = sbase + (uint32_t)(buf * SM_STRIDE + row * GPAD + ldc) * 4;
            cp16(sa, A + (size_t)(bm + row) * K + k0 + ldc);
            uint32_t sb = sbase + (uint32_t)(2 * SM_STRIDE + buf * SM_STRIDE + row * GPAD + ldc) * 4;
            cp16(sb, B + (size_t)(bn + row) * K + k0 + ldc);
        }
        asm volatile("cp.async.commit_group;" ::: "memory");
    };

    loadTiles(0, 0);

    for (int s = 0; s < NS; s++) {
        const int buf = s & 1;
        if (s + 1 < NS) {
            loadTiles((s + 1) * 32, buf ^ 1);
            asm volatile("cp.async.wait_group 1;" ::: "memory");
        } else {
            asm volatile("cp.async.wait_group 0;" ::: "memory");
        }
        __syncthreads();

        const float* As_ = sm + buf * SM_STRIDE;
        const float* Bs_ = sm + 2 * SM_STRIDE + buf * SM_STRIDE;

#pragma unroll
        for (int ks = 0; ks < 4; ks++) {
            uint32_t a[4][4], b[4][2];
#pragma unroll
            for (int i = 0; i < 4; i++) {
                int abase = (wm + i * 16 + gr) * GPAD + ks * 8 + 2 * tc;
                float2 alo = *(const float2*)(As_ + abase);
                float2 ahi = *(const float2*)(As_ + abase + 8 * GPAD);
                a[i][0] = __float_as_uint(alo.x);
                a[i][1] = __float_as_uint(ahi.x);
                a[i][2] = __float_as_uint(alo.y);
                a[i][3] = __float_as_uint(ahi.y);
            }
#pragma unroll
            for (int j = 0; j < 4; j++) {
                int bbase = (wn + j * 8 + gr) * GPAD + ks * 8 + 2 * tc;
                float2 bv = *(const float2*)(Bs_ + bbase);
                b[j][0] = __float_as_uint(bv.x);
                b[j][1] = __float_as_uint(bv.y);
            }
#pragma unroll
            for (int i = 0; i < 4; i++)
#pragma unroll
                for (int j = 0; j < 4; j++)
                    mma8(acc[i][j], a[i], b[j]);
        }
        __syncthreads();
    }

    // Epilogue (pairs (c, c+1) per float2 == RoPE pairs when mode==1)
#pragma unroll
    for (int i = 0; i < 4; i++) {
#pragma unroll
        for (int j = 0; j < 4; j++) {
            int r = bm + wm + i * 16 + gr;
            int c = bn + wn + j * 8 + tc * 2;
            float2 v0 = make_float2(acc[i][j][0], acc[i][j][1]);
            float2 v1 = make_float2(acc[i][j][2], acc[i][j][3]);
            if (mode == 1) {
                if (c < V_OFF) {
                    int i64 = (c >> 1) & 63;
                    float inv = (float)pow(500000.0, -(double)i64 / 64.0);
                    float s0, c0;
                    sincosf((float)r * inv, &s0, &c0);
                    float a0 = v0.x, b0 = v0.y;
                    v0.x = clmp(a0 * c0 - b0 * s0);
                    v0.y = clmp(a0 * s0 + b0 * c0);
                    float s1, c1;
                    sincosf((float)(r + 8) * inv, &s1, &c1);
                    float a1 = v1.x, b1 = v1.y;
                    v1.x = clmp(a1 * c1 - b1 * s1);
                    v1.y = clmp(a1 * s1 + b1 * c1);
                } else {
                    v0.x = clmp(v0.x); v0.y = clmp(v0.y);
                    v1.x = clmp(v1.x); v1.y = clmp(v1.y);
                }
            }
            *(float2*)&C[(size_t)r * N + c]       = v0;
            *(float2*)&C[(size_t)(r + 8) * N + c] = v1;
        }
    }
}

// ===========================================================================
// Tensor-core flash attention. Output written K-PERMUTED + rna-rounded
// (feeds the out-proj GEMM directly).
// ===========================================================================
#define A_QH   0
#define A_QL   34816
#define A_KH   69632
#define A_KL   87040
#define A_VT   104448
#define A_VS   139264
#define A_PH   139264
#define A_SS   174080
#define A_PL   174080
#define A_STAT 208896
#define ATT_SMEM 210432

__global__ __launch_bounds__(256, 1)
void attn_mma_kernel(float* __restrict__ out)
{
    extern __shared__ char smem[];
    uint32_t* QHw = (uint32_t*)(smem + A_QH);
    uint32_t* QLw = (uint32_t*)(smem + A_QL);
    uint32_t* KHw = (uint32_t*)(smem + A_KH);
    uint32_t* KLw = (uint32_t*)(smem + A_KL);
    float*    VT  = (float*)(smem + A_VT);
    float*    VS  = (float*)(smem + A_VS);
    float*    PH  = (float*)(smem + A_PH);
    float*    SS  = (float*)(smem + A_SS);
    float*    PL  = SS;
    float* rowM = (float*)(smem + A_STAT);
    float* rowL = rowM + 128;
    float* rowA = rowL + 128;

    const int qb   = gridDim.x - 1 - blockIdx.x;
    const int h    = blockIdx.y;
    const int kh   = h / REP;
    const int tid  = threadIdx.x;
    const int wid  = tid >> 5, lane = tid & 31;
    const int gr   = lane >> 2, tc = lane & 3;
    const int m0   = (wid >> 1) * 32;
    const int wn   = (wid & 1) * 32;
    const int nv   = (wid & 1) * 64;
    const float scale = 0.088388347648318447f;

    {
        const float* qg = g_qkv + (size_t)(qb * 128) * QKV_N + h * HD;
#pragma unroll
        for (int i = 0; i < 16; i++) {
            int f = tid + i * 256;
            int r = f >> 5;
            int c = (f & 31) * 4;
            float4 v = *(const float4*)(qg + (size_t)r * QKV_N + c);
            uint32_t l0, l1;
            uint32_t h0 = packsplit(v.x, v.y, l0);
            uint32_t h1 = packsplit(v.z, v.w, l1);
            QHw[r * 68 + c / 2]     = h0;
            QHw[r * 68 + c / 2 + 1] = h1;
            QLw[r * 68 + c / 2]     = l0;
            QLw[r * 68 + c / 2 + 1] = l1;
        }
    }
    if (tid < 128) { rowM[tid] = -1e30f; rowL[tid] = 0.f; }

    float o[2][8][4];
#pragma unroll
    for (int mi = 0; mi < 2; mi++)
#pragma unroll
        for (int j = 0; j < 8; j++)
#pragma unroll
            for (int r = 0; r < 4; r++) o[mi][j][r] = 0.f;

    const int nkt = 2 * qb + 2;
    for (int kt = 0; kt < nkt; kt++) {
        __syncthreads();

        {
            const float* kg = g_qkv + (size_t)(kt * 64) * QKV_N + KV_OFF + kh * HD;
            const float* vg = g_qkv + (size_t)(kt * 64) * QKV_N + V_OFF  + kh * HD;
#pragma unroll
            for (int i = 0; i < 8; i++) {
                int f = tid + i * 256;
                int r = f >> 5;
                int c = (f & 31) * 4;
                float4 kv = *(const float4*)(kg + (size_t)r * QKV_N + c);
                uint32_t l0, l1;
                uint32_t h0 = packsplit(kv.x, kv.y, l0);
                uint32_t h1 = packsplit(kv.z, kv.w, l1);
                KHw[r * 68 + c / 2]     = h0;
                KHw[r * 68 + c / 2 + 1] = h1;
                KLw[r * 68 + c / 2]     = l0;
                KLw[r * 68 + c / 2 + 1] = l1;
                float4 vv = *(const float4*)(vg + (size_t)r * QKV_N + c);
                VS[r * 133 + c + 0] = vv.x;
                VS[r * 133 + c + 1] = vv.y;
                VS[r * 133 + c + 2] = vv.z;
                VS[r * 133 + c + 3] = vv.w;
            }
        }
        __syncthreads();

#pragma unroll
        for (int i = 0; i < 32; i++) {
            int widx = wid + 8 * i;
            int d = widx >> 1;
            int r = (widx & 1) * 32 + lane;
            VT[d * 68 + r] = ftf32(VS[r * 133 + d]);
        }

        float sacc[2][4][4];
#pragma unroll
        for (int mi = 0; mi < 2; mi++)
#pragma unroll
            for (int j = 0; j < 4; j++)
#pragma unroll
                for (int r = 0; r < 4; r++) sacc[mi][j][r] = 0.f;

#pragma unroll
        for (int ks = 0; ks < 8; ks++) {
            uint32_t ah[2][4], al[2][4];
#pragma unroll
            for (int mi = 0; mi < 2; mi++) {
                int base = (m0 + mi * 16 + gr) * 68 + ks * 8 + tc;
                ah[mi][0] = QHw[base];
                ah[mi][1] = QHw[base + 8 * 68];
                ah[mi][2] = QHw[base + 4];
                ah[mi][3] = QHw[base + 8 * 68 + 4];
                al[mi][0] = QLw[base];
                al[mi][1] = QLw[base + 8 * 68];
                al[mi][2] = QLw[base + 4];
                al[mi][3] = QLw[base + 8 * 68 + 4];
            }
            uint32_t bh[4][2], bl[4][2];
#pragma unroll
            for (int j = 0; j < 4; j++) {
                int base = (wn + j * 8 + gr) * 68 + ks * 8 + tc;
                bh[j][0] = KHw[base];
                bh[j][1] = KHw[base + 4];
                bl[j][0] = KLw[base];
                bl[j][1] = KLw[base + 4];
            }
#pragma unroll
            for (int mi = 0; mi < 2; mi++)
#pragma unroll
                for (int j = 0; j < 4; j++) {
                    mma16bf(sacc[mi][j], ah[mi], bh[j]);
                    mma16bf(sacc[mi][j], ah[mi], bl[j]);
                    mma16bf(sacc[mi][j], al[mi], bh[j]);
                }
        }

        const bool dg = (kt >= 2 * qb);
#pragma unroll
        for (int mi = 0; mi < 2; mi++) {
#pragma unroll
            for (int j = 0; j < 4; j++) {
                int rl0 = m0 + mi * 16 + gr;
                int cl  = wn + j * 8 + 2 * tc;
                float v0 = sacc[mi][j][0] * scale;
                float v1 = sacc[mi][j][1] * scale;
                float v2 = sacc[mi][j][2] * scale;
                float v3 = sacc[mi][j][3] * scale;
                if (dg) {
                    int rg0 = qb * 128 + rl0;
                    int cg  = kt * 64 + cl;
                    if (cg     > rg0)     v0 = -1e30f;
                    if (cg + 1 > rg0)     v1 = -1e30f;
                    if (cg     > rg0 + 8) v2 = -1e30f;
                    if (cg + 1 > rg0 + 8) v3 = -1e30f;
                }
                *(float2*)&SS[rl0 * 68 + cl]       = make_float2(v0, v1);
                *(float2*)&SS[(rl0 + 8) * 68 + cl] = make_float2(v2, v3);
            }
        }
        __syncthreads();

        if (tid < 128) {
            int r = tid;
            float mOld = rowM[r];
            float m = mOld;
            const float4* srow = (const float4*)(SS + r * 68);
#pragma unroll
            for (int jj = 0; jj < 16; jj++) {
                float4 s4 = srow[jj];
                m = fmaxf(m, fmaxf(fmaxf(s4.x, s4.y), fmaxf(s4.z, s4.w)));
            }
            float alpha = __expf(mOld - m);
            float l = 0.f;
#pragma unroll
            for (int jj = 0; jj < 16; jj++) {
                float4 s4 = srow[jj];
                float p0 = __expf(s4.x - m);
                float p1 = __expf(s4.y - m);
                float p2 = __expf(s4.z - m);
                float p3 = __expf(s4.w - m);
                l += (p0 + p1) + (p2 + p3);
                float h0 = ftf32(p0), h1 = ftf32(p1), h2 = ftf32(p2), h3 = ftf32(p3);
                float4 hv = make_float4(h0, h1, h2, h3);
                float4 lv = make_float4(ftf32(p0 - h0), ftf32(p1 - h1),
                                        ftf32(p2 - h2), ftf32(p3 - h3));
                *(float4*)&PH[r * 68 + jj * 4] = hv;
                *(float4*)&PL[r * 68 + jj * 4] = lv;
            }
            rowL[r] = rowL[r] * alpha + l;
            rowM[r] = m;
            rowA[r] = alpha;
        }
        __syncthreads();

#pragma unroll
        for (int mi = 0; mi < 2; mi++) {
            float am0 = rowA[m0 + mi * 16 + gr];
            float am1 = rowA[m0 + mi * 16 + gr + 8];
#pragma unroll
            for (int j = 0; j < 8; j++) {
                o[mi][j][0] *= am0; o[mi][j][1] *= am0;
                o[mi][j][2] *= am1; o[mi][j][3] *= am1;
            }
        }
#pragma unroll
        for (int ks = 0; ks < 8; ks++) {
            uint32_t ap[2][4], alr[2][4];
#pragma unroll
            for (int mi = 0; mi < 2; mi++) {
                int base = (m0 + mi * 16 + gr) * 68 + ks * 8 + tc;
                ap[mi][0]  = __float_as_uint(PH[base]);
                ap[mi][1]  = __float_as_uint(PH[base + 8 * 68]);
                ap[mi][2]  = __float_as_uint(PH[base + 4]);
                ap[mi][3]  = __float_as_uint(PH[base + 8 * 68 + 4]);
                alr[mi][0] = __float_as_uint(PL[base]);
                alr[mi][1] = __float_as_uint(PL[base + 8 * 68]);
                alr[mi][2] = __float_as_uint(PL[base + 4]);
                alr[mi][3] = __float_as_uint(PL[base + 8 * 68 + 4]);
            }
#pragma unroll
            for (int j = 0; j < 8; j++) {
                int base = (nv + j * 8 + gr) * 68 + ks * 8 + tc;
                uint32_t b[2];
                b[0] = __float_as_uint(VT[base]);
                b[1] = __float_as_uint(VT[base + 4]);
#pragma unroll
                for (int mi = 0; mi < 2; mi++) {
                    mma8(o[mi][j], ap[mi], b);
                    mma8(o[mi][j], alr[mi], b);
                }
            }
        }
    }

    // ---- normalize + rna-round + K-PERMUTED store ----
    // within-8 position: pos(c) = (c<4) ? 2c : 2c-7
    const int p0 = (tc < 2) ? 4 * tc     : 4 * tc - 7;   // pos(2tc)
    const int p1 = (tc < 2) ? 4 * tc + 2 : 4 * tc - 5;   // pos(2tc+1)
#pragma unroll
    for (int mi = 0; mi < 2; mi++) {
        int rl0 = m0 + mi * 16 + gr;
        float inv0 = 1.f / rowL[rl0];
        float inv1 = 1.f / rowL[rl0 + 8];
        int rg0 = qb * 128 + rl0;
#pragma unroll
        for (int j = 0; j < 8; j++) {
            int gbase = h * HD + nv + j * 8;     // 8-aligned group base
            float* d0 = out + (size_t)rg0 * DM + gbase;
            float* d1 = out + (size_t)(rg0 + 8) * DM + gbase;
            d0[p0] = ftf32(o[mi][j][0] * inv0);
            d0[p1] = ftf32(o[mi][j][1] * inv0);
            d1[p0] = ftf32(o[mi][j][2] * inv1);
            d1[p1] = ftf32(o[mi][j][3] * inv1);
        }
    }
}

// ===========================================================================
// Host side
// ===========================================================================
extern "C" void kernel_launch(void* const* d_in, const int* in_sizes, int n_in,
                              void* d_out, int out_size)
{
    const float* x     = (const float*)d_in[0];
    const float* w_qkv = (const float*)d_in[2];
    const float* w_out = (const float*)d_in[3];
    float* out = (float*)d_out;

    float *qkv, *attn, *xp, *wqkvp, *woutp;
    cudaGetSymbolAddress((void**)&qkv,   g_qkv);
    cudaGetSymbolAddress((void**)&attn,  g_attn);
    cudaGetSymbolAddress((void**)&xp,    g_xp);
    cudaGetSymbolAddress((void**)&wqkvp, g_wqkvp);
    cudaGetSymbolAddress((void**)&woutp, g_woutp);

    cudaFuncSetAttribute(gemm_mma, cudaFuncAttributeMaxDynamicSharedMemorySize,
                         GEMM_SMEM_BYTES);
    cudaFuncSetAttribute(attn_mma_kernel, cudaFuncAttributeMaxDynamicSharedMemorySize,
                         ATT_SMEM);

    // 0) permute + rna-round GEMM operands
    {
        int n8x = TT * DM / 8;
        perm_round_kernel<<<(n8x + 255) / 256, 256>>>((const float4*)x, (float4*)xp, n8x);
        int n8q = QKV_N * DM / 8;
        perm_round_kernel<<<(n8q + 255) / 256, 256>>>((const float4*)w_qkv, (float4*)wqkvp, n8q);
        int n8o = DM * DM / 8;
        perm_round_kernel<<<(n8o + 255) / 256, 256>>>((const float4*)w_out, (float4*)woutp, n8o);
    }

    // 1) QKV projection + fused RoPE/clamp epilogue
    {
        dim3 grid(QKV_N / 128, TT / 128);
        gemm_mma<<<grid, 256, GEMM_SMEM_BYTES>>>(xp, wqkvp, qkv, QKV_N, DM, 1);
    }

    // 2) Tensor-core flash attention (writes permuted + rounded)
    {
        dim3 grid(TT / 128, NH);
        attn_mma_kernel<<<grid, 256, ATT_SMEM>>>(attn);
    }

    // 3) Output projection
    {
        dim3 grid(DM / 128, TT / 128);
        gemm_mma<<<grid, 256, GEMM_SMEM_BYTES>>>(attn, woutp, out, DM, DM, 0);
    }
}